// round 5
// baseline (speedup 1.0000x reference)
#include <cuda_runtime.h>
#include <cstdint>

#define NNODES 50000
#define NPAD   50048          // divisible by 64 and 128
#define NE     800000
#define DIN    128
#define DHID   256

// ---------------- scratch (device globals: allocation-free) ----------------
// Declared as float4 arrays: guarantees 16B alignment for LDG.128/STG.128/RED.128.
__device__ float  g_deg [NPAD];
__device__ float  g_dinv[NPAD];
__device__ float4 g_agg1[NPAD * DIN / 4];    // aggregated x       [N,128]
__device__ float4 g_h1  [NPAD * DHID / 4];   // relu(agg1@W1^T+b1) [N,256]
__device__ float4 g_h2  [NPAD * DIN / 4];    // h1@W2^T            [N,128]
__device__ float4 g_agg2[NPAD * DIN / 4];    // aggregated h2      [N,128]
__device__ float4 g_W1t [DIN * DHID / 4];    // W1^T: [K=128][NOUT=256]
__device__ float4 g_W2t [DHID * DIN / 4];    // W2^T: [K=256][NOUT=128]

// ---------------- helpers ----------------
__device__ __forceinline__ void red_add_v4(float* addr, float4 v) {
    asm volatile("red.global.add.v4.f32 [%0], {%1,%2,%3,%4};"
                 :: "l"(addr), "f"(v.x), "f"(v.y), "f"(v.z), "f"(v.w)
                 : "memory");
}

// ---------------- degree / norm ----------------
__global__ void k_deg_init(float* deg) {
    int i = blockIdx.x * blockDim.x + threadIdx.x;
    if (i < NPAD) deg[i] = (i < NNODES) ? 1.0f : 0.0f;   // self-loop weight
}

__global__ void k_deg_acc(const int* __restrict__ ei,
                          const float* __restrict__ ew,
                          float* deg) {
    int e = blockIdx.x * blockDim.x + threadIdx.x;
    if (e < NE) atomicAdd(&deg[ei[NE + e]], ew[e]);
}

__global__ void k_dinv(const float* __restrict__ deg, float* dinv) {
    int i = blockIdx.x * blockDim.x + threadIdx.x;
    if (i < NPAD) {
        float d = deg[i];
        dinv[i] = (i < NNODES && d > 0.f) ? rsqrtf(d) : 0.f;
    }
}

// agg1[i] = x[i] * dinv[i]^2  (self-loop contribution; zeros pad rows)
__global__ void k_selfinit1(const float* __restrict__ x,
                            const float* __restrict__ dinv,
                            float4* __restrict__ agg1) {
    int idx = blockIdx.x * blockDim.x + threadIdx.x;   // one float4 each
    if (idx >= NPAD * (DIN / 4)) return;
    int node = idx >> 5;          // DIN/4 = 32
    int c4   = idx & 31;
    float4 v = make_float4(0.f, 0.f, 0.f, 0.f);
    if (node < NNODES) {
        float di = dinv[node];
        float s  = di * di;
        float4 xv = *(const float4*)(x + (size_t)node * DIN + c4 * 4);
        v = make_float4(xv.x * s, xv.y * s, xv.z * s, xv.w * s);
    }
    agg1[idx] = v;
}

// ---------------- weight transpose [NOUT,K] -> [K,NOUT] ----------------
__global__ void k_transpose(const float* __restrict__ W, float* __restrict__ Wt,
                            int nout, int k) {
    int idx = blockIdx.x * blockDim.x + threadIdx.x;
    if (idx < nout * k) {
        int n = idx / k, kk = idx % k;
        Wt[kk * nout + n] = W[idx];
    }
}

// ---------------- edge aggregation: warp per edge, D=128 ----------------
__global__ void __launch_bounds__(256)
k_agg_edges(const int* __restrict__ ei,
            const float* __restrict__ ew,
            const float* __restrict__ dinv,
            const float* __restrict__ feat,   // [*,128], 16B-aligned
            float* __restrict__ agg) {        // [*,128], 16B-aligned
    int warp = (blockIdx.x * blockDim.x + threadIdx.x) >> 5;
    int lane = threadIdx.x & 31;
    if (warp >= NE) return;
    int s = __ldg(&ei[warp]);
    int d = __ldg(&ei[NE + warp]);
    float norm = __ldg(&dinv[s]) * __ldg(&ew[warp]) * __ldg(&dinv[d]);
    float4 v = __ldg((const float4*)(feat + (size_t)s * DIN + lane * 4));
    v.x *= norm; v.y *= norm; v.z *= norm; v.w *= norm;
    red_add_v4(agg + (size_t)d * DIN + lane * 4, v);
}

// ---------------- register-tiled fp32 GEMM: C[M,NOUT] = A[M,K] @ Bt[K,NOUT] ----
// MODE 1: C = relu(acc + bias)             (layer-1 epilogue)
// MODE 2: C = acc; agg2 = acc * dinv^2     (layer-2 epilogue, self-loop init)
template<int K, int NOUT, int NT_N, int NT_M, int KCHUNK, int MODE>
__global__ void __launch_bounds__(256, 1)
k_gemm(const float* __restrict__ A,
       const float* __restrict__ Bt,
       const float* __restrict__ bias,
       float* __restrict__ C,
       const float* __restrict__ dinv,
       float* __restrict__ agg2) {
    constexpr int TM = 8, TN = 8;
    constexpr int MTILE = NT_M * TM;
    extern __shared__ float smem[];
    float* sB = smem;                  // K * NOUT
    float* sA = smem + K * NOUT;       // MTILE * KCHUNK

    const int tid = threadIdx.x;
    const int tx = tid % NT_N;
    const int ty = tid / NT_N;
    const int row0 = blockIdx.x * MTILE;

    // load full Bt (contiguous, float4)
    {
        const float4* src = (const float4*)Bt;
        float4* dst = (float4*)sB;
        constexpr int TOT = K * NOUT / 4;
        #pragma unroll 4
        for (int i = tid; i < TOT; i += 256) dst[i] = src[i];
    }

    float acc[TM][TN];
    #pragma unroll
    for (int i = 0; i < TM; ++i)
        #pragma unroll
        for (int j = 0; j < TN; ++j) acc[i][j] = 0.f;

    constexpr int NCH = K / KCHUNK;
    for (int ch = 0; ch < NCH; ++ch) {
        __syncthreads();
        // load A chunk [MTILE x KCHUNK], coalesced float4 row copies
        {
            constexpr int C4 = KCHUNK / 4;
            #pragma unroll 4
            for (int i = tid; i < MTILE * C4; i += 256) {
                int r = i / C4, c = i % C4;
                ((float4*)sA)[i] =
                    *(const float4*)(A + (size_t)(row0 + r) * K + ch * KCHUNK + c * 4);
            }
        }
        __syncthreads();

        #pragma unroll
        for (int k4 = 0; k4 < KCHUNK / 4; ++k4) {
            float4 a4[TM];
            #pragma unroll
            for (int i = 0; i < TM; ++i)
                a4[i] = *(const float4*)(sA + (ty * TM + i) * KCHUNK + k4 * 4);
            #pragma unroll
            for (int kk = 0; kk < 4; ++kk) {
                const int kg = ch * KCHUNK + k4 * 4 + kk;
                float4 b0 = *(const float4*)(sB + kg * NOUT + tx * TN);
                float4 b1 = *(const float4*)(sB + kg * NOUT + tx * TN + 4);
                #pragma unroll
                for (int i = 0; i < TM; ++i) {
                    float av = (kk == 0) ? a4[i].x : (kk == 1) ? a4[i].y
                             : (kk == 2) ? a4[i].z : a4[i].w;
                    acc[i][0] += av * b0.x; acc[i][1] += av * b0.y;
                    acc[i][2] += av * b0.z; acc[i][3] += av * b0.w;
                    acc[i][4] += av * b1.x; acc[i][5] += av * b1.y;
                    acc[i][6] += av * b1.z; acc[i][7] += av * b1.w;
                }
            }
        }
    }

    // epilogue
    #pragma unroll
    for (int i = 0; i < TM; ++i) {
        const int row = row0 + ty * TM + i;
        float d2 = 0.f;
        if (MODE == 2) { float di = dinv[row]; d2 = di * di; }
        #pragma unroll
        for (int jj = 0; jj < TN; jj += 4) {
            const int col = tx * TN + jj;
            float4 v = make_float4(acc[i][jj], acc[i][jj+1], acc[i][jj+2], acc[i][jj+3]);
            if (MODE == 1) {
                float4 b = __ldg((const float4*)(bias + col));
                v.x = fmaxf(v.x + b.x, 0.f); v.y = fmaxf(v.y + b.y, 0.f);
                v.z = fmaxf(v.z + b.z, 0.f); v.w = fmaxf(v.w + b.w, 0.f);
                *(float4*)(C + (size_t)row * NOUT + col) = v;
            } else {
                *(float4*)(C + (size_t)row * NOUT + col) = v;
                float4 w = make_float4(v.x * d2, v.y * d2, v.z * d2, v.w * d2);
                *(float4*)(agg2 + (size_t)row * NOUT + col) = w;
            }
        }
    }
}

// ---------------- LayerNorm: warp per node, 4 floats per lane ----------------
__global__ void __launch_bounds__(256)
k_layernorm(const float* __restrict__ agg2,
            const float* __restrict__ b2,
            const float* __restrict__ gamma,
            const float* __restrict__ beta,
            float* __restrict__ out) {
    int node = (blockIdx.x * blockDim.x + threadIdx.x) >> 5;
    int lane = threadIdx.x & 31;
    if (node >= NNODES) return;
    float4 v = *(const float4*)(agg2 + (size_t)node * DIN + lane * 4);
    float4 bb = __ldg((const float4*)(b2 + lane * 4));
    v.x += bb.x; v.y += bb.y; v.z += bb.z; v.w += bb.w;

    float s = v.x + v.y + v.z + v.w;
    #pragma unroll
    for (int o = 16; o; o >>= 1) s += __shfl_xor_sync(0xFFFFFFFFu, s, o);
    const float mu = s * (1.0f / DIN);

    float4 d = make_float4(v.x - mu, v.y - mu, v.z - mu, v.w - mu);
    float q = d.x * d.x + d.y * d.y + d.z * d.z + d.w * d.w;
    #pragma unroll
    for (int o = 16; o; o >>= 1) q += __shfl_xor_sync(0xFFFFFFFFu, q, o);
    const float r = rsqrtf(q * (1.0f / DIN) + 1e-5f);

    float4 g = __ldg((const float4*)(gamma + lane * 4));
    float4 be = __ldg((const float4*)(beta + lane * 4));
    float4 o4;
    o4.x = d.x * r * g.x + be.x;
    o4.y = d.y * r * g.y + be.y;
    o4.z = d.z * r * g.z + be.z;
    o4.w = d.w * r * g.w + be.w;
    *(float4*)(out + (size_t)node * DIN + lane * 4) = o4;
}

// ---------------- launch ----------------
extern "C" void kernel_launch(void* const* d_in, const int* in_sizes, int n_in,
                              void* d_out, int out_size) {
    const float* x  = (const float*)d_in[0];
    const int*   ei = (const int*)d_in[1];     // int32! (JAX x64 disabled)
    const float* ew = (const float*)d_in[2];
    const float* W1 = (const float*)d_in[3];
    const float* b1 = (const float*)d_in[4];
    const float* W2 = (const float*)d_in[5];
    const float* b2 = (const float*)d_in[6];
    const float* gm = (const float*)d_in[7];
    const float* bt = (const float*)d_in[8];
    float* out = (float*)d_out;

    float *p_deg, *p_dinv;
    float4 *p_agg1, *p_h1, *p_h2, *p_agg2, *p_W1t, *p_W2t;
    cudaGetSymbolAddress((void**)&p_deg,  g_deg);
    cudaGetSymbolAddress((void**)&p_dinv, g_dinv);
    cudaGetSymbolAddress((void**)&p_agg1, g_agg1);
    cudaGetSymbolAddress((void**)&p_h1,   g_h1);
    cudaGetSymbolAddress((void**)&p_h2,   g_h2);
    cudaGetSymbolAddress((void**)&p_agg2, g_agg2);
    cudaGetSymbolAddress((void**)&p_W1t,  g_W1t);
    cudaGetSymbolAddress((void**)&p_W2t,  g_W2t);

    // GEMM1: K=128, NOUT=256, NT_N=32, NT_M=8  (MTILE=64),  smem=160KB
    // GEMM2: K=256, NOUT=128, NT_N=16, NT_M=16 (MTILE=128), smem=192KB
    const int smem1 = (DIN * DHID + 64 * 128) * 4;
    const int smem2 = (DHID * DIN + 128 * 128) * 4;
    cudaFuncSetAttribute((const void*)k_gemm<128, 256, 32, 8, 128, 1>,
                         cudaFuncAttributeMaxDynamicSharedMemorySize, smem1);
    cudaFuncSetAttribute((const void*)k_gemm<256, 128, 16, 16, 128, 2>,
                         cudaFuncAttributeMaxDynamicSharedMemorySize, smem2);

    // 1) degrees (self loop = 1.0) + dinv
    k_deg_init<<<(NPAD + 255) / 256, 256>>>(p_deg);
    k_deg_acc <<<(NE + 255) / 256, 256>>>(ei, ew, p_deg);
    k_dinv    <<<(NPAD + 255) / 256, 256>>>(p_deg, p_dinv);

    // 2) weight transposes (tiny)
    k_transpose<<<(DHID * DIN + 255) / 256, 256>>>(W1, (float*)p_W1t, DHID, DIN);
    k_transpose<<<(DIN * DHID + 255) / 256, 256>>>(W2, (float*)p_W2t, DIN, DHID);

    // 3) layer 1: aggregate x (self-loop init + edge scatter), then GEMM+bias+relu
    k_selfinit1<<<(NPAD * (DIN / 4) + 255) / 256, 256>>>(x, p_dinv, p_agg1);
    k_agg_edges<<<(NE * 32) / 256, 256>>>(ei, ew, p_dinv, x, (float*)p_agg1);
    k_gemm<128, 256, 32, 8, 128, 1><<<NPAD / 64, 256, smem1>>>(
        (const float*)p_agg1, (const float*)p_W1t, b1, (float*)p_h1, nullptr, nullptr);

    // 4) layer 2: GEMM first (epilogue seeds agg2 with self-loop term), then scatter
    k_gemm<256, 128, 16, 16, 128, 2><<<NPAD / 128, 256, smem2>>>(
        (const float*)p_h1, (const float*)p_W2t, nullptr, (float*)p_h2,
        p_dinv, (float*)p_agg2);
    k_agg_edges<<<(NE * 32) / 256, 256>>>(ei, ew, p_dinv, (float*)p_h2, (float*)p_agg2);

    // 5) bias + LayerNorm
    k_layernorm<<<(NNODES * 32 + 255) / 256, 256>>>((const float*)p_agg2, b2, gm, bt, out);
}

// round 7
// speedup vs baseline: 1.3533x; 1.3533x over previous
#include <cuda_runtime.h>
#include <cstdint>

#define NNODES 50000
#define NPAD   50048          // divisible by 64 and 128
#define NE     800000
#define DIN    128
#define DHID   256
#define SCAN_BS 1024
#define SCAN_NBLK ((NPAD + SCAN_BS - 1) / SCAN_BS)   // 49

// ---------------- scratch (device globals: allocation-free) ----------------
__device__ float  g_degw[NPAD];
__device__ float  g_dinv[NPAD];
__device__ int    g_cnt [NPAD];
__device__ int    g_fill[NPAD];
__device__ int    g_part[NPAD];          // per-element exclusive scan within block
__device__ int    g_bsum[SCAN_NBLK];
__device__ int    g_off [NPAD + 64];     // CSR row offsets
__device__ float2 g_meta[NE];            // (src bits, norm) per CSR slot
__device__ float4 g_agg1[NPAD * DIN / 4];    // aggregated x       [N,128]
__device__ float4 g_h1  [NPAD * DHID / 4];   // relu(agg1@W1^T+b1) [N,256]
__device__ float4 g_h2  [NPAD * DIN / 4];    // h1@W2^T            [N,128]
__device__ float4 g_agg2[NPAD * DIN / 4];    // aggregated h2      [N,128]
__device__ float4 g_W1t [DIN * DHID / 4];    // W1^T: [K=128][NOUT=256]
__device__ float4 g_W2t [DHID * DIN / 4];    // W2^T: [K=256][NOUT=128]

// ---------------- CSR build ----------------
__global__ void k_zero(int* cnt, int* fill, float* degw) {
    int i = blockIdx.x * blockDim.x + threadIdx.x;
    if (i < NPAD) {
        cnt[i] = 0; fill[i] = 0;
        degw[i] = (i < NNODES) ? 1.0f : 0.0f;   // self-loop weight
    }
}

__global__ void k_hist(const int* __restrict__ ei,
                       const float* __restrict__ ew,
                       int* cnt, float* degw) {
    int e = blockIdx.x * blockDim.x + threadIdx.x;
    if (e < NE) {
        int d = ei[NE + e];
        atomicAdd(&cnt[d], 1);
        atomicAdd(&degw[d], ew[e]);
    }
}

__global__ void k_dinv(const float* __restrict__ degw, float* dinv) {
    int i = blockIdx.x * blockDim.x + threadIdx.x;
    if (i < NPAD) {
        float d = degw[i];
        dinv[i] = (i < NNODES && d > 0.f) ? rsqrtf(d) : 0.f;
    }
}

// scan A: per-block exclusive scan (Hillis-Steele) + block sums
__global__ void k_scanA(const int* __restrict__ cnt, int* part, int* bsum) {
    __shared__ int sh[SCAN_BS];
    int i = blockIdx.x * SCAN_BS + threadIdx.x;
    int v = (i < NPAD) ? cnt[i] : 0;
    sh[threadIdx.x] = v;
    __syncthreads();
    #pragma unroll
    for (int off = 1; off < SCAN_BS; off <<= 1) {
        int t = (threadIdx.x >= off) ? sh[threadIdx.x - off] : 0;
        __syncthreads();
        sh[threadIdx.x] += t;
        __syncthreads();
    }
    if (i < NPAD) part[i] = sh[threadIdx.x] - v;          // exclusive
    if (threadIdx.x == SCAN_BS - 1) bsum[blockIdx.x] = sh[SCAN_BS - 1];
}

// scan B: exclusive scan of SCAN_NBLK block sums (single block)
__global__ void k_scanB(int* bsum) {
    __shared__ int sh[64];
    int v = (threadIdx.x < SCAN_NBLK) ? bsum[threadIdx.x] : 0;
    sh[threadIdx.x] = v;
    __syncthreads();
    #pragma unroll
    for (int off = 1; off < 64; off <<= 1) {
        int t = (threadIdx.x >= off) ? sh[threadIdx.x - off] : 0;
        __syncthreads();
        sh[threadIdx.x] += t;
        __syncthreads();
    }
    if (threadIdx.x < SCAN_NBLK) bsum[threadIdx.x] = sh[threadIdx.x] - v;
}

// scan C: combine
__global__ void k_scanC(const int* __restrict__ part,
                        const int* __restrict__ bsum, int* off) {
    int i = blockIdx.x * blockDim.x + threadIdx.x;
    if (i < NPAD) off[i] = part[i] + bsum[i >> 10];
    if (i == 0) off[NPAD] = NE;
}

// fill CSR slots with (src, norm)
__global__ void k_fill(const int* __restrict__ ei,
                       const float* __restrict__ ew,
                       const float* __restrict__ dinv,
                       const int* __restrict__ off,
                       int* fill, float2* meta) {
    int e = blockIdx.x * blockDim.x + threadIdx.x;
    if (e >= NE) return;
    int s = ei[e];
    int d = ei[NE + e];
    int pos = off[d] + atomicAdd(&fill[d], 1);
    float nm = dinv[s] * ew[e] * dinv[d];
    meta[pos] = make_float2(__int_as_float(s), nm);
}

// ---------------- CSR aggregation: warp per node, D=128 ----------------
// acc = dinv[n]^2 * feat[n] + sum_{e in CSR[n]} norm_e * feat[src_e]
__global__ void __launch_bounds__(256)
k_agg_csr(const int* __restrict__ off,
          const float2* __restrict__ meta,
          const float* __restrict__ dinv,
          const float* __restrict__ feat,   // [*,128], 16B-aligned
          float* __restrict__ aggout) {     // [NPAD,128]
    int node = (blockIdx.x * blockDim.x + threadIdx.x) >> 5;
    int lane = threadIdx.x & 31;
    if (node >= NPAD) return;

    float4 acc = make_float4(0.f, 0.f, 0.f, 0.f);
    if (node < NNODES) {
        float di = __ldg(&dinv[node]);
        float d2 = di * di;
        float4 sv = __ldg((const float4*)(feat + (size_t)node * DIN + lane * 4));
        acc.x = sv.x * d2; acc.y = sv.y * d2; acc.z = sv.z * d2; acc.w = sv.w * d2;
    }

    const int e0 = __ldg(&off[node]);
    const int e1 = __ldg(&off[node + 1]);
    for (int t = e0; t < e1; t += 4) {
        // uniform (warp-broadcast) meta loads, predicated against tail
        float2 m0 = make_float2(0.f, 0.f), m1 = m0, m2 = m0, m3 = m0;
        m0 = __ldg(&meta[t]);
        if (t + 1 < e1) m1 = __ldg(&meta[t + 1]);
        if (t + 2 < e1) m2 = __ldg(&meta[t + 2]);
        if (t + 3 < e1) m3 = __ldg(&meta[t + 3]);
        int s0 = __float_as_int(m0.x), s1 = __float_as_int(m1.x);
        int s2 = __float_as_int(m2.x), s3 = __float_as_int(m3.x);
        // 4 independent 128-bit gathers in flight
        float4 v0 = __ldg((const float4*)(feat + (size_t)s0 * DIN + lane * 4));
        float4 v1 = __ldg((const float4*)(feat + (size_t)s1 * DIN + lane * 4));
        float4 v2 = __ldg((const float4*)(feat + (size_t)s2 * DIN + lane * 4));
        float4 v3 = __ldg((const float4*)(feat + (size_t)s3 * DIN + lane * 4));
        acc.x += v0.x * m0.y; acc.y += v0.y * m0.y; acc.z += v0.z * m0.y; acc.w += v0.w * m0.y;
        acc.x += v1.x * m1.y; acc.y += v1.y * m1.y; acc.z += v1.z * m1.y; acc.w += v1.w * m1.y;
        acc.x += v2.x * m2.y; acc.y += v2.y * m2.y; acc.z += v2.z * m2.y; acc.w += v2.w * m2.y;
        acc.x += v3.x * m3.y; acc.y += v3.y * m3.y; acc.z += v3.z * m3.y; acc.w += v3.w * m3.y;
    }
    *(float4*)(aggout + (size_t)node * DIN + lane * 4) = acc;
}

// ---------------- weight transpose [NOUT,K] -> [K,NOUT] ----------------
__global__ void k_transpose(const float* __restrict__ W, float* __restrict__ Wt,
                            int nout, int k) {
    int idx = blockIdx.x * blockDim.x + threadIdx.x;
    if (idx < nout * k) {
        int n = idx / k, kk = idx % k;
        Wt[kk * nout + n] = W[idx];
    }
}

// ---------------- register-tiled fp32 GEMM: C[M,NOUT] = A[M,K] @ Bt[K,NOUT] ----
// MODE 1: C = relu(acc + bias)   (layer-1 epilogue)
// MODE 0: C = acc                (layer-2: plain store)
template<int K, int NOUT, int NT_N, int NT_M, int KCHUNK, int MODE>
__global__ void __launch_bounds__(256, 1)
k_gemm(const float* __restrict__ A,
       const float* __restrict__ Bt,
       const float* __restrict__ bias,
       float* __restrict__ C) {
    constexpr int TM = 8, TN = 8;
    constexpr int MTILE = NT_M * TM;
    extern __shared__ float smem[];
    float* sB = smem;                  // K * NOUT
    float* sA = smem + K * NOUT;       // MTILE * KCHUNK

    const int tid = threadIdx.x;
    const int tx = tid % NT_N;
    const int ty = tid / NT_N;
    const int row0 = blockIdx.x * MTILE;

    // load full Bt (contiguous, float4)
    {
        const float4* src = (const float4*)Bt;
        float4* dst = (float4*)sB;
        constexpr int TOT = K * NOUT / 4;
        #pragma unroll 4
        for (int i = tid; i < TOT; i += 256) dst[i] = src[i];
    }

    float acc[TM][TN];
    #pragma unroll
    for (int i = 0; i < TM; ++i)
        #pragma unroll
        for (int j = 0; j < TN; ++j) acc[i][j] = 0.f;

    constexpr int NCH = K / KCHUNK;
    for (int ch = 0; ch < NCH; ++ch) {
        __syncthreads();
        {
            constexpr int C4 = KCHUNK / 4;
            #pragma unroll 4
            for (int i = tid; i < MTILE * C4; i += 256) {
                int r = i / C4, c = i % C4;
                ((float4*)sA)[i] =
                    *(const float4*)(A + (size_t)(row0 + r) * K + ch * KCHUNK + c * 4);
            }
        }
        __syncthreads();

        #pragma unroll
        for (int k4 = 0; k4 < KCHUNK / 4; ++k4) {
            float4 a4[TM];
            #pragma unroll
            for (int i = 0; i < TM; ++i)
                a4[i] = *(const float4*)(sA + (ty * TM + i) * KCHUNK + k4 * 4);
            #pragma unroll
            for (int kk = 0; kk < 4; ++kk) {
                const int kg = ch * KCHUNK + k4 * 4 + kk;
                float4 b0 = *(const float4*)(sB + kg * NOUT + tx * TN);
                float4 b1 = *(const float4*)(sB + kg * NOUT + tx * TN + 4);
                #pragma unroll
                for (int i = 0; i < TM; ++i) {
                    float av = (kk == 0) ? a4[i].x : (kk == 1) ? a4[i].y
                             : (kk == 2) ? a4[i].z : a4[i].w;
                    acc[i][0] += av * b0.x; acc[i][1] += av * b0.y;
                    acc[i][2] += av * b0.z; acc[i][3] += av * b0.w;
                    acc[i][4] += av * b1.x; acc[i][5] += av * b1.y;
                    acc[i][6] += av * b1.z; acc[i][7] += av * b1.w;
                }
            }
        }
    }

    #pragma unroll
    for (int i = 0; i < TM; ++i) {
        const int row = row0 + ty * TM + i;
        #pragma unroll
        for (int jj = 0; jj < TN; jj += 4) {
            const int col = tx * TN + jj;
            float4 v = make_float4(acc[i][jj], acc[i][jj+1], acc[i][jj+2], acc[i][jj+3]);
            if (MODE == 1) {
                float4 b = __ldg((const float4*)(bias + col));
                v.x = fmaxf(v.x + b.x, 0.f); v.y = fmaxf(v.y + b.y, 0.f);
                v.z = fmaxf(v.z + b.z, 0.f); v.w = fmaxf(v.w + b.w, 0.f);
            }
            *(float4*)(C + (size_t)row * NOUT + col) = v;
        }
    }
}

// ---------------- LayerNorm: warp per node, 4 floats per lane ----------------
__global__ void __launch_bounds__(256)
k_layernorm(const float* __restrict__ agg2,
            const float* __restrict__ b2,
            const float* __restrict__ gamma,
            const float* __restrict__ beta,
            float* __restrict__ out) {
    int node = (blockIdx.x * blockDim.x + threadIdx.x) >> 5;
    int lane = threadIdx.x & 31;
    if (node >= NNODES) return;
    float4 v = *(const float4*)(agg2 + (size_t)node * DIN + lane * 4);
    float4 bb = __ldg((const float4*)(b2 + lane * 4));
    v.x += bb.x; v.y += bb.y; v.z += bb.z; v.w += bb.w;

    float s = v.x + v.y + v.z + v.w;
    #pragma unroll
    for (int o = 16; o; o >>= 1) s += __shfl_xor_sync(0xFFFFFFFFu, s, o);
    const float mu = s * (1.0f / DIN);

    float4 d = make_float4(v.x - mu, v.y - mu, v.z - mu, v.w - mu);
    float q = d.x * d.x + d.y * d.y + d.z * d.z + d.w * d.w;
    #pragma unroll
    for (int o = 16; o; o >>= 1) q += __shfl_xor_sync(0xFFFFFFFFu, q, o);
    const float r = rsqrtf(q * (1.0f / DIN) + 1e-5f);

    float4 g = __ldg((const float4*)(gamma + lane * 4));
    float4 be = __ldg((const float4*)(beta + lane * 4));
    float4 o4;
    o4.x = d.x * r * g.x + be.x;
    o4.y = d.y * r * g.y + be.y;
    o4.z = d.z * r * g.z + be.z;
    o4.w = d.w * r * g.w + be.w;
    *(float4*)(out + (size_t)node * DIN + lane * 4) = o4;
}

// ---------------- launch ----------------
extern "C" void kernel_launch(void* const* d_in, const int* in_sizes, int n_in,
                              void* d_out, int out_size) {
    const float* x  = (const float*)d_in[0];
    const int*   ei = (const int*)d_in[1];     // int32 (JAX x64 disabled)
    const float* ew = (const float*)d_in[2];
    const float* W1 = (const float*)d_in[3];
    const float* b1 = (const float*)d_in[4];
    const float* W2 = (const float*)d_in[5];
    const float* b2 = (const float*)d_in[6];
    const float* gm = (const float*)d_in[7];
    const float* bt = (const float*)d_in[8];
    float* out = (float*)d_out;

    float *p_degw, *p_dinv;
    int *p_cnt, *p_fill, *p_part, *p_bsum, *p_off;
    float2 *p_meta;
    float4 *p_agg1, *p_h1, *p_h2, *p_agg2, *p_W1t, *p_W2t;
    cudaGetSymbolAddress((void**)&p_degw, g_degw);
    cudaGetSymbolAddress((void**)&p_dinv, g_dinv);
    cudaGetSymbolAddress((void**)&p_cnt,  g_cnt);
    cudaGetSymbolAddress((void**)&p_fill, g_fill);
    cudaGetSymbolAddress((void**)&p_part, g_part);
    cudaGetSymbolAddress((void**)&p_bsum, g_bsum);
    cudaGetSymbolAddress((void**)&p_off,  g_off);
    cudaGetSymbolAddress((void**)&p_meta, g_meta);
    cudaGetSymbolAddress((void**)&p_agg1, g_agg1);
    cudaGetSymbolAddress((void**)&p_h1,   g_h1);
    cudaGetSymbolAddress((void**)&p_h2,   g_h2);
    cudaGetSymbolAddress((void**)&p_agg2, g_agg2);
    cudaGetSymbolAddress((void**)&p_W1t,  g_W1t);
    cudaGetSymbolAddress((void**)&p_W2t,  g_W2t);

    // GEMM1: K=128, NOUT=256, NT_N=32, NT_M=8  (MTILE=64),  smem=160KB
    // GEMM2: K=256, NOUT=128, NT_N=16, NT_M=16 (MTILE=128), smem=192KB
    const int smem1 = (DIN * DHID + 64 * 128) * 4;
    const int smem2 = (DHID * DIN + 128 * 128) * 4;
    cudaFuncSetAttribute((const void*)k_gemm<128, 256, 32, 8, 128, 1>,
                         cudaFuncAttributeMaxDynamicSharedMemorySize, smem1);
    cudaFuncSetAttribute((const void*)k_gemm<256, 128, 16, 16, 128, 0>,
                         cudaFuncAttributeMaxDynamicSharedMemorySize, smem2);

    const int TB = 256;
    // weight transposes (independent)
    k_transpose<<<(DHID * DIN + TB - 1) / TB, TB>>>(W1, (float*)p_W1t, DHID, DIN);
    k_transpose<<<(DIN * DHID + TB - 1) / TB, TB>>>(W2, (float*)p_W2t, DIN, DHID);

    // CSR build + norms
    k_zero <<<(NPAD + TB - 1) / TB, TB>>>(p_cnt, p_fill, p_degw);
    k_hist <<<(NE + TB - 1) / TB, TB>>>(ei, ew, p_cnt, p_degw);
    k_dinv <<<(NPAD + TB - 1) / TB, TB>>>(p_degw, p_dinv);
    k_scanA<<<SCAN_NBLK, SCAN_BS>>>(p_cnt, p_part, p_bsum);
    k_scanB<<<1, 64>>>(p_bsum);
    k_scanC<<<(NPAD + TB - 1) / TB, TB>>>(p_part, p_bsum, p_off);
    k_fill <<<(NE + TB - 1) / TB, TB>>>(ei, ew, p_dinv, p_off, p_fill, p_meta);

    // layer 1: aggregate x (CSR), then GEMM + bias + relu
    k_agg_csr<<<NPAD / 8, TB>>>(p_off, p_meta, p_dinv, x, (float*)p_agg1);
    k_gemm<128, 256, 32, 8, 128, 1><<<NPAD / 64, 256, smem1>>>(
        (const float*)p_agg1, (const float*)p_W1t, b1, (float*)p_h1);

    // layer 2: GEMM first, then aggregate (CSR)
    k_gemm<256, 128, 16, 16, 128, 0><<<NPAD / 128, 256, smem2>>>(
        (const float*)p_h1, (const float*)p_W2t, nullptr, (float*)p_h2);
    k_agg_csr<<<NPAD / 8, TB>>>(p_off, p_meta, p_dinv, (float*)p_h2, (float*)p_agg2);

    // bias + LayerNorm
    k_layernorm<<<(NNODES * 32 + TB - 1) / TB, TB>>>(
        (const float*)p_agg2, b2, gm, bt, out);
}

// round 13
// speedup vs baseline: 1.4034x; 1.0370x over previous
#include <cuda_runtime.h>
#include <cstdint>

#define NNODES 50000
#define NPAD   50048          // divisible by 64 and 128
#define NE     800000
#define DIN    128
#define DHID   256
#define SCAN_BS 1024
#define SCAN_NBLK ((NPAD + SCAN_BS - 1) / SCAN_BS)   // 49

// ---------------- scratch (device globals: allocation-free) ----------------
__device__ float  g_degw[NPAD];
__device__ float  g_dinv[NPAD];
__device__ int    g_cnt [NPAD];
__device__ int    g_fill[NPAD];
__device__ int    g_part[NPAD];
__device__ int    g_bsum[SCAN_NBLK];
__device__ int    g_off [NPAD + 64];
__device__ float2 g_meta[NE];
__device__ float4 g_agg1[NPAD * DIN / 4];
__device__ float4 g_h1  [NPAD * DHID / 4];
__device__ float4 g_h2  [NPAD * DIN / 4];
__device__ float4 g_agg2[NPAD * DIN / 4];
__device__ float4 g_W1t [DIN * DHID / 4];
__device__ float4 g_W2t [DHID * DIN / 4];

// ---------------- f32x2 packed-FMA helpers (PTX ISA 8.6, sm_100+ base) -----
__device__ __forceinline__ void fma2(unsigned long long& acc,
                                     unsigned long long a, unsigned long long b) {
    asm("fma.rn.f32x2 %0, %1, %2, %0;" : "+l"(acc) : "l"(a), "l"(b));
}
__device__ __forceinline__ unsigned long long pack2(float lo, float hi) {
    unsigned long long r;
    asm("mov.b64 %0, {%1, %2};" : "=l"(r) : "f"(lo), "f"(hi));
    return r;
}
__device__ __forceinline__ float2 unpack2(unsigned long long v) {
    float lo, hi;
    asm("mov.b64 {%0, %1}, %2;" : "=f"(lo), "=f"(hi) : "l"(v));
    return make_float2(lo, hi);
}

// ---------------- CSR build ----------------
__global__ void k_zero(int* cnt, int* fill, float* degw) {
    int i = blockIdx.x * blockDim.x + threadIdx.x;
    if (i < NPAD) { cnt[i] = 0; fill[i] = 0; degw[i] = (i < NNODES) ? 1.0f : 0.0f; }
}
__global__ void k_hist(const int* __restrict__ ei, const float* __restrict__ ew,
                       int* cnt, float* degw) {
    int e = blockIdx.x * blockDim.x + threadIdx.x;
    if (e < NE) {
        int d = ei[NE + e];
        atomicAdd(&cnt[d], 1);
        atomicAdd(&degw[d], ew[e]);
    }
}
__global__ void k_dinv(const float* __restrict__ degw, float* dinv) {
    int i = blockIdx.x * blockDim.x + threadIdx.x;
    if (i < NPAD) {
        float d = degw[i];
        dinv[i] = (i < NNODES && d > 0.f) ? rsqrtf(d) : 0.f;
    }
}
__global__ void k_scanA(const int* __restrict__ cnt, int* part, int* bsum) {
    __shared__ int sh[SCAN_BS];
    int i = blockIdx.x * SCAN_BS + threadIdx.x;
    int v = (i < NPAD) ? cnt[i] : 0;
    sh[threadIdx.x] = v;
    __syncthreads();
    #pragma unroll
    for (int off = 1; off < SCAN_BS; off <<= 1) {
        int t = (threadIdx.x >= off) ? sh[threadIdx.x - off] : 0;
        __syncthreads();
        sh[threadIdx.x] += t;
        __syncthreads();
    }
    if (i < NPAD) part[i] = sh[threadIdx.x] - v;
    if (threadIdx.x == SCAN_BS - 1) bsum[blockIdx.x] = sh[SCAN_BS - 1];
}
__global__ void k_scanB(int* bsum) {
    __shared__ int sh[64];
    int v = (threadIdx.x < SCAN_NBLK) ? bsum[threadIdx.x] : 0;
    sh[threadIdx.x] = v;
    __syncthreads();
    #pragma unroll
    for (int off = 1; off < 64; off <<= 1) {
        int t = (threadIdx.x >= off) ? sh[threadIdx.x - off] : 0;
        __syncthreads();
        sh[threadIdx.x] += t;
        __syncthreads();
    }
    if (threadIdx.x < SCAN_NBLK) bsum[threadIdx.x] = sh[threadIdx.x] - v;
}
__global__ void k_scanC(const int* __restrict__ part, const int* __restrict__ bsum, int* off) {
    int i = blockIdx.x * blockDim.x + threadIdx.x;
    if (i < NPAD) off[i] = part[i] + bsum[i >> 10];
    if (i == 0) off[NPAD] = NE;
}
__global__ void k_fill(const int* __restrict__ ei, const float* __restrict__ ew,
                       const float* __restrict__ dinv, const int* __restrict__ off,
                       int* fill, float2* meta) {
    int e = blockIdx.x * blockDim.x + threadIdx.x;
    if (e >= NE) return;
    int s = ei[e];
    int d = ei[NE + e];
    int pos = off[d] + atomicAdd(&fill[d], 1);
    meta[pos] = make_float2(__int_as_float(s), dinv[s] * ew[e] * dinv[d]);
}

// ---------------- CSR aggregation: warp per node, D=128 ----------------
__global__ void __launch_bounds__(256)
k_agg_csr(const int* __restrict__ off, const float2* __restrict__ meta,
          const float* __restrict__ dinv, const float* __restrict__ feat,
          float* __restrict__ aggout) {
    int node = (blockIdx.x * blockDim.x + threadIdx.x) >> 5;
    int lane = threadIdx.x & 31;
    if (node >= NPAD) return;

    float4 acc = make_float4(0.f, 0.f, 0.f, 0.f);
    if (node < NNODES) {
        float di = __ldg(&dinv[node]);
        float d2 = di * di;
        float4 sv = __ldg((const float4*)(feat + (size_t)node * DIN + lane * 4));
        acc.x = sv.x * d2; acc.y = sv.y * d2; acc.z = sv.z * d2; acc.w = sv.w * d2;
    }
    const int e0 = __ldg(&off[node]);
    const int e1 = __ldg(&off[node + 1]);
    for (int t = e0; t < e1; t += 4) {
        float2 m0 = make_float2(0.f, 0.f), m1 = m0, m2 = m0, m3 = m0;
        m0 = __ldg(&meta[t]);
        if (t + 1 < e1) m1 = __ldg(&meta[t + 1]);
        if (t + 2 < e1) m2 = __ldg(&meta[t + 2]);
        if (t + 3 < e1) m3 = __ldg(&meta[t + 3]);
        int s0 = __float_as_int(m0.x), s1 = __float_as_int(m1.x);
        int s2 = __float_as_int(m2.x), s3 = __float_as_int(m3.x);
        float4 v0 = __ldg((const float4*)(feat + (size_t)s0 * DIN + lane * 4));
        float4 v1 = __ldg((const float4*)(feat + (size_t)s1 * DIN + lane * 4));
        float4 v2 = __ldg((const float4*)(feat + (size_t)s2 * DIN + lane * 4));
        float4 v3 = __ldg((const float4*)(feat + (size_t)s3 * DIN + lane * 4));
        acc.x += v0.x * m0.y; acc.y += v0.y * m0.y; acc.z += v0.z * m0.y; acc.w += v0.w * m0.y;
        acc.x += v1.x * m1.y; acc.y += v1.y * m1.y; acc.z += v1.z * m1.y; acc.w += v1.w * m1.y;
        acc.x += v2.x * m2.y; acc.y += v2.y * m2.y; acc.z += v2.z * m2.y; acc.w += v2.w * m2.y;
        acc.x += v3.x * m3.y; acc.y += v3.y * m3.y; acc.z += v3.z * m3.y; acc.w += v3.w * m3.y;
    }
    *(float4*)(aggout + (size_t)node * DIN + lane * 4) = acc;
}

// ---------------- weight transpose [NOUT,K] -> [K,NOUT] ----------------
__global__ void k_transpose(const float* __restrict__ W, float* __restrict__ Wt,
                            int nout, int k) {
    int idx = blockIdx.x * blockDim.x + threadIdx.x;
    if (idx < nout * k) {
        int n = idx / k, kk = idx % k;
        Wt[kk * nout + n] = W[idx];
    }
}

// ---------------- register-tiled GEMM with packed f32x2 FMA ----------------
// C[M,NOUT] = A[M,K] @ Bt[K,NOUT]
// MODE 1: C = relu(acc + bias)   (layer-1 epilogue)
// MODE 0: C = acc                (layer-2: plain store)
template<int K, int NOUT, int NT_N, int NT_M, int KCHUNK, int MODE>
__global__ void __launch_bounds__(256, 1)
k_gemm(const float* __restrict__ A,
       const float* __restrict__ Bt,
       const float* __restrict__ bias,
       float* __restrict__ C) {
    constexpr int TM = 8, TN = 8;
    constexpr int MTILE = NT_M * TM;
    extern __shared__ float smem[];
    float* sB = smem;                  // K * NOUT
    float* sA = smem + K * NOUT;       // MTILE * KCHUNK

    const int tid = threadIdx.x;
    const int tx = tid % NT_N;
    const int ty = tid / NT_N;
    const int row0 = blockIdx.x * MTILE;

    // load full Bt (contiguous, float4)
    {
        const float4* src = (const float4*)Bt;
        float4* dst = (float4*)sB;
        constexpr int TOT = K * NOUT / 4;
        #pragma unroll 4
        for (int i = tid; i < TOT; i += 256) dst[i] = src[i];
    }

    // packed accumulators: acc2[i][p] holds columns (2p, 2p+1)
    unsigned long long acc2[TM][TN / 2];
    #pragma unroll
    for (int i = 0; i < TM; ++i)
        #pragma unroll
        for (int p = 0; p < TN / 2; ++p) acc2[i][p] = 0ULL;

    constexpr int NCH = K / KCHUNK;
    for (int ch = 0; ch < NCH; ++ch) {
        __syncthreads();
        // load A chunk [MTILE x KCHUNK], coalesced float4 row copies
        {
            constexpr int C4 = KCHUNK / 4;
            #pragma unroll 4
            for (int i = tid; i < MTILE * C4; i += 256) {
                int r = i / C4, c = i % C4;
                ((float4*)sA)[i] =
                    *(const float4*)(A + (size_t)(row0 + r) * K + ch * KCHUNK + c * 4);
            }
        }
        __syncthreads();

        #pragma unroll
        for (int k4 = 0; k4 < KCHUNK / 4; ++k4) {
            float4 a4[TM];
            #pragma unroll
            for (int i = 0; i < TM; ++i)
                a4[i] = *(const float4*)(sA + (ty * TM + i) * KCHUNK + k4 * 4);
            #pragma unroll
            for (int kk = 0; kk < 4; ++kk) {
                const int kg = ch * KCHUNK + k4 * 4 + kk;
                // B pairs as packed f32x2 lanes straight from smem (16B loads)
                const ulonglong2 bA = *(const ulonglong2*)(sB + kg * NOUT + tx * TN);
                const ulonglong2 bB = *(const ulonglong2*)(sB + kg * NOUT + tx * TN + 4);
                #pragma unroll
                for (int i = 0; i < TM; ++i) {
                    float av = (kk == 0) ? a4[i].x : (kk == 1) ? a4[i].y
                             : (kk == 2) ? a4[i].z : a4[i].w;
                    unsigned long long av2 = pack2(av, av);
                    fma2(acc2[i][0], av2, bA.x);
                    fma2(acc2[i][1], av2, bA.y);
                    fma2(acc2[i][2], av2, bB.x);
                    fma2(acc2[i][3], av2, bB.y);
                }
            }
        }
    }

    // epilogue
    #pragma unroll
    for (int i = 0; i < TM; ++i) {
        const int row = row0 + ty * TM + i;
        #pragma unroll
        for (int jj = 0; jj < TN; jj += 4) {
            const int col = tx * TN + jj;
            float2 p0 = unpack2(acc2[i][jj / 2]);
            float2 p1 = unpack2(acc2[i][jj / 2 + 1]);
            float4 v = make_float4(p0.x, p0.y, p1.x, p1.y);
            if (MODE == 1) {
                float4 b = __ldg((const float4*)(bias + col));
                v.x = fmaxf(v.x + b.x, 0.f); v.y = fmaxf(v.y + b.y, 0.f);
                v.z = fmaxf(v.z + b.z, 0.f); v.w = fmaxf(v.w + b.w, 0.f);
            }
            *(float4*)(C + (size_t)row * NOUT + col) = v;
        }
    }
}

// ---------------- LayerNorm: warp per node, 4 floats per lane ----------------
__global__ void __launch_bounds__(256)
k_layernorm(const float* __restrict__ agg2, const float* __restrict__ b2,
            const float* __restrict__ gamma, const float* __restrict__ beta,
            float* __restrict__ out) {
    int node = (blockIdx.x * blockDim.x + threadIdx.x) >> 5;
    int lane = threadIdx.x & 31;
    if (node >= NNODES) return;
    float4 v = *(const float4*)(agg2 + (size_t)node * DIN + lane * 4);
    float4 bb = __ldg((const float4*)(b2 + lane * 4));
    v.x += bb.x; v.y += bb.y; v.z += bb.z; v.w += bb.w;

    float s = v.x + v.y + v.z + v.w;
    #pragma unroll
    for (int o = 16; o; o >>= 1) s += __shfl_xor_sync(0xFFFFFFFFu, s, o);
    const float mu = s * (1.0f / DIN);

    float4 d = make_float4(v.x - mu, v.y - mu, v.z - mu, v.w - mu);
    float q = d.x * d.x + d.y * d.y + d.z * d.z + d.w * d.w;
    #pragma unroll
    for (int o = 16; o; o >>= 1) q += __shfl_xor_sync(0xFFFFFFFFu, q, o);
    const float r = rsqrtf(q * (1.0f / DIN) + 1e-5f);

    float4 g = __ldg((const float4*)(gamma + lane * 4));
    float4 be = __ldg((const float4*)(beta + lane * 4));
    float4 o4;
    o4.x = d.x * r * g.x + be.x;
    o4.y = d.y * r * g.y + be.y;
    o4.z = d.z * r * g.z + be.z;
    o4.w = d.w * r * g.w + be.w;
    *(float4*)(out + (size_t)node * DIN + lane * 4) = o4;
}

// ---------------- launch ----------------
extern "C" void kernel_launch(void* const* d_in, const int* in_sizes, int n_in,
                              void* d_out, int out_size) {
    const float* x  = (const float*)d_in[0];
    const int*   ei = (const int*)d_in[1];     // int32 (JAX x64 disabled)
    const float* ew = (const float*)d_in[2];
    const float* W1 = (const float*)d_in[3];
    const float* b1 = (const float*)d_in[4];
    const float* W2 = (const float*)d_in[5];
    const float* b2 = (const float*)d_in[6];
    const float* gm = (const float*)d_in[7];
    const float* bt = (const float*)d_in[8];
    float* out = (float*)d_out;

    float *p_degw, *p_dinv;
    int *p_cnt, *p_fill, *p_part, *p_bsum, *p_off;
    float2* p_meta;
    float4 *p_agg1, *p_h1, *p_h2, *p_agg2, *p_W1t, *p_W2t;
    cudaGetSymbolAddress((void**)&p_degw, g_degw);
    cudaGetSymbolAddress((void**)&p_dinv, g_dinv);
    cudaGetSymbolAddress((void**)&p_cnt,  g_cnt);
    cudaGetSymbolAddress((void**)&p_fill, g_fill);
    cudaGetSymbolAddress((void**)&p_part, g_part);
    cudaGetSymbolAddress((void**)&p_bsum, g_bsum);
    cudaGetSymbolAddress((void**)&p_off,  g_off);
    cudaGetSymbolAddress((void**)&p_meta, g_meta);
    cudaGetSymbolAddress((void**)&p_agg1, g_agg1);
    cudaGetSymbolAddress((void**)&p_h1,   g_h1);
    cudaGetSymbolAddress((void**)&p_h2,   g_h2);
    cudaGetSymbolAddress((void**)&p_agg2, g_agg2);
    cudaGetSymbolAddress((void**)&p_W1t,  g_W1t);
    cudaGetSymbolAddress((void**)&p_W2t,  g_W2t);

    // GEMM1: K=128, NOUT=256, NT_N=32, NT_M=8  (MTILE=64),  smem=160KB
    // GEMM2: K=256, NOUT=128, NT_N=16, NT_M=16 (MTILE=128), smem=192KB
    const int smem1 = (DIN * DHID + 64 * 128) * 4;
    const int smem2 = (DHID * DIN + 128 * 128) * 4;
    cudaFuncSetAttribute((const void*)k_gemm<128, 256, 32, 8, 128, 1>,
                         cudaFuncAttributeMaxDynamicSharedMemorySize, smem1);
    cudaFuncSetAttribute((const void*)k_gemm<256, 128, 16, 16, 128, 0>,
                         cudaFuncAttributeMaxDynamicSharedMemorySize, smem2);

    const int TB = 256;
    // weight transposes (independent, tiny)
    k_transpose<<<(DHID * DIN + TB - 1) / TB, TB>>>(W1, (float*)p_W1t, DHID, DIN);
    k_transpose<<<(DIN * DHID + TB - 1) / TB, TB>>>(W2, (float*)p_W2t, DIN, DHID);

    // CSR build + norms
    k_zero <<<(NPAD + TB - 1) / TB, TB>>>(p_cnt, p_fill, p_degw);
    k_hist <<<(NE + TB - 1) / TB, TB>>>(ei, ew, p_cnt, p_degw);
    k_dinv <<<(NPAD + TB - 1) / TB, TB>>>(p_degw, p_dinv);
    k_scanA<<<SCAN_NBLK, SCAN_BS>>>(p_cnt, p_part, p_bsum);
    k_scanB<<<1, 64>>>(p_bsum);
    k_scanC<<<(NPAD + TB - 1) / TB, TB>>>(p_part, p_bsum, p_off);
    k_fill <<<(NE + TB - 1) / TB, TB>>>(ei, ew, p_dinv, p_off, p_fill, p_meta);

    // layer 1: aggregate x (CSR), then GEMM + bias + relu
    k_agg_csr<<<NPAD / 8, TB>>>(p_off, p_meta, p_dinv, x, (float*)p_agg1);
    k_gemm<128, 256, 32, 8, 128, 1><<<NPAD / 64, 256, smem1>>>(
        (const float*)p_agg1, (const float*)p_W1t, b1, (float*)p_h1);

    // layer 2: GEMM first, then aggregate (CSR)
    k_gemm<256, 128, 16, 16, 128, 0><<<NPAD / 128, 256, smem2>>>(
        (const float*)p_h1, (const float*)p_W2t, nullptr, (float*)p_h2);
    k_agg_csr<<<NPAD / 8, TB>>>(p_off, p_meta, p_dinv, (const float*)p_h2,
                                (float*)p_agg2);

    // bias + LayerNorm
    k_layernorm<<<(NNODES * 32 + TB - 1) / TB, TB>>>(
        (const float*)p_agg2, b2, gm, bt, out);
}

// round 15
// speedup vs baseline: 1.9261x; 1.3724x over previous
#include <cuda_runtime.h>
#include <cuda_bf16.h>
#include <cstdint>

#define NNODES 50000
#define NPAD   50048          // 391 * 128
#define NTILES 391
#define NE     800000
#define DIN    128
#define DHID   256
#define SCAN_BS 1024
#define SCAN_NBLK ((NPAD + SCAN_BS - 1) / SCAN_BS)   // 49

// ---------------- scratch (device globals: allocation-free) ----------------
__device__ float    g_degw[NPAD];
__device__ float    g_dinv[NPAD];
__device__ int      g_cnt [NPAD];
__device__ int      g_fill[NPAD];
__device__ int      g_part[NPAD];
__device__ int      g_bsum[SCAN_NBLK];
__device__ int      g_off [NPAD + 64];
__device__ float2   g_meta[NE];
// planar bf16 split operands — declared uint4 for guaranteed 16B alignment
// (uint4 = 8 packed bf16)
__device__ uint4    g_a1h[NPAD * DIN / 8];    // agg1 hi  [N][128]
__device__ uint4    g_a1l[NPAD * DIN / 8];    // agg1 lo
__device__ uint4    g_h1h[NPAD * DHID / 8];   // h1 hi    [N][256]
__device__ uint4    g_h1l[NPAD * DHID / 8];   // h1 lo
__device__ uint4    g_w1h[DHID * DIN / 8];    // W1 hi    [256][128]
__device__ uint4    g_w1l[DHID * DIN / 8];
__device__ uint4    g_w2h[DIN * DHID / 8];    // W2 hi    [128][256]
__device__ uint4    g_w2l[DIN * DHID / 8];
__device__ float4   g_h2  [NPAD * DIN / 4];   // GEMM2 out fp32 [N][128]
__device__ float4   g_agg2[NPAD * DIN / 4];   // aggregated h2  [N][128]

// ---------------- helpers ----------------
__device__ __forceinline__ uint32_t pack_bf2(__nv_bfloat16 a, __nv_bfloat16 b) {
    return (uint32_t)__bfloat16_as_ushort(a) | ((uint32_t)__bfloat16_as_ushort(b) << 16);
}
__device__ __forceinline__ void split_bf(float v, __nv_bfloat16& h, __nv_bfloat16& l) {
    h = __float2bfloat16_rn(v);
    l = __float2bfloat16_rn(v - __bfloat162float(h));
}
__device__ __forceinline__ void mma_bf16(float* c, const uint32_t* a,
                                         uint32_t b0, uint32_t b1) {
    asm volatile("mma.sync.aligned.m16n8k16.row.col.f32.bf16.bf16.f32 "
                 "{%0,%1,%2,%3}, {%4,%5,%6,%7}, {%8,%9}, {%0,%1,%2,%3};"
                 : "+f"(c[0]), "+f"(c[1]), "+f"(c[2]), "+f"(c[3])
                 : "r"(a[0]), "r"(a[1]), "r"(a[2]), "r"(a[3]), "r"(b0), "r"(b1));
}

// ---------------- CSR build ----------------
__global__ void k_zero(int* cnt, int* fill, float* degw) {
    int i = blockIdx.x * blockDim.x + threadIdx.x;
    if (i < NPAD) { cnt[i] = 0; fill[i] = 0; degw[i] = (i < NNODES) ? 1.0f : 0.0f; }
}
__global__ void k_hist(const int* __restrict__ ei, const float* __restrict__ ew,
                       int* cnt, float* degw) {
    int e = blockIdx.x * blockDim.x + threadIdx.x;
    if (e < NE) {
        int d = ei[NE + e];
        atomicAdd(&cnt[d], 1);
        atomicAdd(&degw[d], ew[e]);
    }
}
__global__ void k_dinv(const float* __restrict__ degw, float* dinv) {
    int i = blockIdx.x * blockDim.x + threadIdx.x;
    if (i < NPAD) {
        float d = degw[i];
        dinv[i] = (i < NNODES && d > 0.f) ? rsqrtf(d) : 0.f;
    }
}
__global__ void k_scanA(const int* __restrict__ cnt, int* part, int* bsum) {
    __shared__ int sh[SCAN_BS];
    int i = blockIdx.x * SCAN_BS + threadIdx.x;
    int v = (i < NPAD) ? cnt[i] : 0;
    sh[threadIdx.x] = v;
    __syncthreads();
    #pragma unroll
    for (int off = 1; off < SCAN_BS; off <<= 1) {
        int t = (threadIdx.x >= off) ? sh[threadIdx.x - off] : 0;
        __syncthreads();
        sh[threadIdx.x] += t;
        __syncthreads();
    }
    if (i < NPAD) part[i] = sh[threadIdx.x] - v;
    if (threadIdx.x == SCAN_BS - 1) bsum[blockIdx.x] = sh[SCAN_BS - 1];
}
__global__ void k_scanB(int* bsum) {
    __shared__ int sh[64];
    int v = (threadIdx.x < SCAN_NBLK) ? bsum[threadIdx.x] : 0;
    sh[threadIdx.x] = v;
    __syncthreads();
    #pragma unroll
    for (int off = 1; off < 64; off <<= 1) {
        int t = (threadIdx.x >= off) ? sh[threadIdx.x - off] : 0;
        __syncthreads();
        sh[threadIdx.x] += t;
        __syncthreads();
    }
    if (threadIdx.x < SCAN_NBLK) bsum[threadIdx.x] = sh[threadIdx.x] - v;
}
__global__ void k_scanC(const int* __restrict__ part, const int* __restrict__ bsum, int* off) {
    int i = blockIdx.x * blockDim.x + threadIdx.x;
    if (i < NPAD) off[i] = part[i] + bsum[i >> 10];
    if (i == 0) off[NPAD] = NE;
}
__global__ void k_fill(const int* __restrict__ ei, const float* __restrict__ ew,
                       const float* __restrict__ dinv, const int* __restrict__ off,
                       int* fill, float2* meta) {
    int e = blockIdx.x * blockDim.x + threadIdx.x;
    if (e >= NE) return;
    int s = ei[e];
    int d = ei[NE + e];
    int pos = off[d] + atomicAdd(&fill[d], 1);
    meta[pos] = make_float2(__int_as_float(s), dinv[s] * ew[e] * dinv[d]);
}

// ---------------- weight split: fp32 row-major -> planar bf16 hi/lo ----------
// one thread = 8 consecutive floats = 1 uint4 of packed bf16 per plane
__global__ void k_prepW(const float* __restrict__ W, uint4* __restrict__ oh,
                        uint4* __restrict__ ol, int total8) {
    int idx = blockIdx.x * blockDim.x + threadIdx.x;
    if (idx >= total8) return;
    uint4 ph, pl;
    uint32_t* hp = (uint32_t*)&ph;
    uint32_t* lp = (uint32_t*)&pl;
    #pragma unroll
    for (int p = 0; p < 4; ++p) {
        float v0 = W[idx * 8 + p * 2];
        float v1 = W[idx * 8 + p * 2 + 1];
        __nv_bfloat16 h0, l0, h1, l1;
        split_bf(v0, h0, l0);
        split_bf(v1, h1, l1);
        hp[p] = pack_bf2(h0, h1);
        lp[p] = pack_bf2(l0, l1);
    }
    oh[idx] = ph;
    ol[idx] = pl;
}

// ---------------- CSR aggregation: warp per node, D=128 ----------------
// SPLIT=1: write planar bf16 hi/lo [NPAD][128]; SPLIT=0: fp32 [NPAD][128]
template<int SPLIT>
__global__ void __launch_bounds__(256)
k_agg_csr(const int* __restrict__ off, const float2* __restrict__ meta,
          const float* __restrict__ dinv, const float* __restrict__ feat,
          float* __restrict__ aggf, uint32_t* __restrict__ oh,
          uint32_t* __restrict__ ol) {
    int node = (blockIdx.x * blockDim.x + threadIdx.x) >> 5;
    int lane = threadIdx.x & 31;
    if (node >= NPAD) return;

    float4 acc = make_float4(0.f, 0.f, 0.f, 0.f);
    if (node < NNODES) {
        float di = __ldg(&dinv[node]);
        float d2 = di * di;
        float4 sv = __ldg((const float4*)(feat + (size_t)node * DIN + lane * 4));
        acc.x = sv.x * d2; acc.y = sv.y * d2; acc.z = sv.z * d2; acc.w = sv.w * d2;
    }
    const int e0 = __ldg(&off[node]);
    const int e1 = __ldg(&off[node + 1]);
    for (int t = e0; t < e1; t += 4) {
        float2 m0 = make_float2(0.f, 0.f), m1 = m0, m2 = m0, m3 = m0;
        m0 = __ldg(&meta[t]);
        if (t + 1 < e1) m1 = __ldg(&meta[t + 1]);
        if (t + 2 < e1) m2 = __ldg(&meta[t + 2]);
        if (t + 3 < e1) m3 = __ldg(&meta[t + 3]);
        int s0 = __float_as_int(m0.x), s1 = __float_as_int(m1.x);
        int s2 = __float_as_int(m2.x), s3 = __float_as_int(m3.x);
        float4 v0 = __ldg((const float4*)(feat + (size_t)s0 * DIN + lane * 4));
        float4 v1 = __ldg((const float4*)(feat + (size_t)s1 * DIN + lane * 4));
        float4 v2 = __ldg((const float4*)(feat + (size_t)s2 * DIN + lane * 4));
        float4 v3 = __ldg((const float4*)(feat + (size_t)s3 * DIN + lane * 4));
        acc.x += v0.x * m0.y; acc.y += v0.y * m0.y; acc.z += v0.z * m0.y; acc.w += v0.w * m0.y;
        acc.x += v1.x * m1.y; acc.y += v1.y * m1.y; acc.z += v1.z * m1.y; acc.w += v1.w * m1.y;
        acc.x += v2.x * m2.y; acc.y += v2.y * m2.y; acc.z += v2.z * m2.y; acc.w += v2.w * m2.y;
        acc.x += v3.x * m3.y; acc.y += v3.y * m3.y; acc.z += v3.z * m3.y; acc.w += v3.w * m3.y;
    }

    if (SPLIT) {
        __nv_bfloat16 hx, lx, hy, ly, hz, lz, hw, lw;
        split_bf(acc.x, hx, lx); split_bf(acc.y, hy, ly);
        split_bf(acc.z, hz, lz); split_bf(acc.w, hw, lw);
        size_t base = (size_t)node * (DIN / 2) + lane * 2;   // u32 units, 8B-aligned
        *(uint2*)(oh + base) = make_uint2(pack_bf2(hx, hy), pack_bf2(hz, hw));
        *(uint2*)(ol + base) = make_uint2(pack_bf2(lx, ly), pack_bf2(lz, lw));
    } else {
        *(float4*)(aggf + (size_t)node * DIN + lane * 4) = acc;
    }
}

// ---------------- bf16-split GEMM via mma.sync m16n8k16 ----------------
// C[128 rows/tile][NOUT] = A[.,KTOT] @ W[NOUT,KTOT]^T, A/W planar bf16 hi/lo.
// 512 threads = 16 warps (4M x 4N). Warp tile 32 x (NOUT/4).
// MODE 1: relu(acc+bias) -> split -> planar hi/lo (next GEMM's A)
// MODE 0: acc -> fp32 row-major [*,NOUT]
template<int KTOT, int NOUT, int MODE>
__global__ void __launch_bounds__(512, 1)
k_gemm_mma(const uint4* __restrict__ aHi, const uint4* __restrict__ aLo,
           const uint4* __restrict__ bHi, const uint4* __restrict__ bLo,
           const float* __restrict__ bias,
           uint32_t* __restrict__ oHi, uint32_t* __restrict__ oLo,
           float* __restrict__ oF) {
    constexpr int NFR = NOUT / 32;       // n-frags per warp (8 or 4)
    constexpr int PB  = KTOT + 8;        // padded B row (elems; bytes %16==0, banks %32==4)
    constexpr int PA  = 136;             // padded A row (272B: 16B-aligned, bank-friendly)
    constexpr int NCH = KTOT / 128;
    constexpr int BU4R = KTOT / 8;       // uint4 per B row

    extern __shared__ __align__(16) __nv_bfloat16 sm[];
    __nv_bfloat16* sBh = sm;                         // NOUT * PB
    __nv_bfloat16* sBl = sBh + NOUT * PB;
    __nv_bfloat16* sAh = sBl + NOUT * PB;            // 128 * PA
    __nv_bfloat16* sAl = sAh + 128 * PA;

    const int tid  = threadIdx.x;
    const int w    = tid >> 5;
    const int lane = tid & 31;
    const int wm   = w >> 2, wn = w & 3;
    const int m0   = wm * 32;
    const int n0   = wn * (NOUT / 4);
    const int gid  = lane >> 2, tq = lane & 3;
    const int tile = blockIdx.x;

    // ---- load full weight (hi+lo) into smem, padded rows (16B stores, aligned) ----
    for (int i = tid; i < NOUT * BU4R; i += 512) {
        int row = i / BU4R, c = i % BU4R;
        *(uint4*)(sBh + row * PB + c * 8) = __ldg(&bHi[i]);
        *(uint4*)(sBl + row * PB + c * 8) = __ldg(&bLo[i]);
    }

    float acc[2][NFR][4];
    #pragma unroll
    for (int i = 0; i < 2; ++i)
        #pragma unroll
        for (int j = 0; j < NFR; ++j)
            #pragma unroll
            for (int q = 0; q < 4; ++q) acc[i][j][q] = 0.f;

    for (int ch = 0; ch < NCH; ++ch) {
        // ---- load A chunk [128 rows][128 cols], hi+lo ----
        for (int i = tid; i < 128 * 16; i += 512) {
            int row = i >> 4, c = i & 15;
            size_t src = ((size_t)tile * 128 + row) * BU4R + ch * 16 + c;
            *(uint4*)(sAh + row * PA + c * 8) = __ldg(&aHi[src]);
            *(uint4*)(sAl + row * PA + c * 8) = __ldg(&aLo[src]);
        }
        __syncthreads();

        #pragma unroll
        for (int ks = 0; ks < 8; ++ks) {
            const int k0 = ks * 16;            // within A chunk
            const int kb = ch * 128 + k0;      // within B row
            uint32_t ah[2][4], al[2][4];
            #pragma unroll
            for (int i = 0; i < 2; ++i) {
                const int r0 = m0 + i * 16 + gid;
                ah[i][0] = *(const uint32_t*)(sAh + r0 * PA + k0 + tq * 2);
                ah[i][1] = *(const uint32_t*)(sAh + (r0 + 8) * PA + k0 + tq * 2);
                ah[i][2] = *(const uint32_t*)(sAh + r0 * PA + k0 + 8 + tq * 2);
                ah[i][3] = *(const uint32_t*)(sAh + (r0 + 8) * PA + k0 + 8 + tq * 2);
                al[i][0] = *(const uint32_t*)(sAl + r0 * PA + k0 + tq * 2);
                al[i][1] = *(const uint32_t*)(sAl + (r0 + 8) * PA + k0 + tq * 2);
                al[i][2] = *(const uint32_t*)(sAl + r0 * PA + k0 + 8 + tq * 2);
                al[i][3] = *(const uint32_t*)(sAl + (r0 + 8) * PA + k0 + 8 + tq * 2);
            }
            #pragma unroll
            for (int j = 0; j < NFR; ++j) {
                const int nr = n0 + j * 8 + gid;
                uint32_t bh0 = *(const uint32_t*)(sBh + nr * PB + kb + tq * 2);
                uint32_t bh1 = *(const uint32_t*)(sBh + nr * PB + kb + 8 + tq * 2);
                uint32_t bl0 = *(const uint32_t*)(sBl + nr * PB + kb + tq * 2);
                uint32_t bl1 = *(const uint32_t*)(sBl + nr * PB + kb + 8 + tq * 2);
                #pragma unroll
                for (int i = 0; i < 2; ++i) {
                    mma_bf16(acc[i][j], ah[i], bh0, bh1);
                    mma_bf16(acc[i][j], ah[i], bl0, bl1);
                    mma_bf16(acc[i][j], al[i], bh0, bh1);
                }
            }
        }
        __syncthreads();
    }

    // ---- epilogue ----
    #pragma unroll
    for (int i = 0; i < 2; ++i) {
        #pragma unroll
        for (int j = 0; j < NFR; ++j) {
            const int c  = n0 + j * 8 + tq * 2;
            #pragma unroll
            for (int h = 0; h < 2; ++h) {      // h=0: row gid, h=1: row gid+8
                const int r = m0 + i * 16 + gid + h * 8;
                const size_t node = (size_t)tile * 128 + r;
                float v0 = acc[i][j][h * 2 + 0];
                float v1 = acc[i][j][h * 2 + 1];
                if (MODE == 1) {
                    v0 = fmaxf(v0 + __ldg(&bias[c]), 0.f);
                    v1 = fmaxf(v1 + __ldg(&bias[c + 1]), 0.f);
                    __nv_bfloat16 h0, l0, h1, l1;
                    split_bf(v0, h0, l0);
                    split_bf(v1, h1, l1);
                    size_t slot = node * (NOUT / 2) + c / 2;
                    oHi[slot] = pack_bf2(h0, h1);
                    oLo[slot] = pack_bf2(l0, l1);
                } else {
                    *(float2*)(oF + node * NOUT + c) = make_float2(v0, v1);
                }
            }
        }
    }
}

// ---------------- LayerNorm: warp per node ----------------
__global__ void __launch_bounds__(256)
k_layernorm(const float* __restrict__ agg2, const float* __restrict__ b2,
            const float* __restrict__ gamma, const float* __restrict__ beta,
            float* __restrict__ out) {
    int node = (blockIdx.x * blockDim.x + threadIdx.x) >> 5;
    int lane = threadIdx.x & 31;
    if (node >= NNODES) return;
    float4 v = *(const float4*)(agg2 + (size_t)node * DIN + lane * 4);
    float4 bb = __ldg((const float4*)(b2 + lane * 4));
    v.x += bb.x; v.y += bb.y; v.z += bb.z; v.w += bb.w;

    float s = v.x + v.y + v.z + v.w;
    #pragma unroll
    for (int o = 16; o; o >>= 1) s += __shfl_xor_sync(0xFFFFFFFFu, s, o);
    const float mu = s * (1.0f / DIN);

    float4 d = make_float4(v.x - mu, v.y - mu, v.z - mu, v.w - mu);
    float q = d.x * d.x + d.y * d.y + d.z * d.z + d.w * d.w;
    #pragma unroll
    for (int o = 16; o; o >>= 1) q += __shfl_xor_sync(0xFFFFFFFFu, q, o);
    const float r = rsqrtf(q * (1.0f / DIN) + 1e-5f);

    float4 g = __ldg((const float4*)(gamma + lane * 4));
    float4 be = __ldg((const float4*)(beta + lane * 4));
    float4 o4;
    o4.x = d.x * r * g.x + be.x;
    o4.y = d.y * r * g.y + be.y;
    o4.z = d.z * r * g.z + be.z;
    o4.w = d.w * r * g.w + be.w;
    *(float4*)(out + (size_t)node * DIN + lane * 4) = o4;
}

// ---------------- launch ----------------
extern "C" void kernel_launch(void* const* d_in, const int* in_sizes, int n_in,
                              void* d_out, int out_size) {
    const float* x  = (const float*)d_in[0];
    const int*   ei = (const int*)d_in[1];     // int32 (JAX x64 disabled)
    const float* ew = (const float*)d_in[2];
    const float* W1 = (const float*)d_in[3];
    const float* b1 = (const float*)d_in[4];
    const float* W2 = (const float*)d_in[5];
    const float* b2 = (const float*)d_in[6];
    const float* gm = (const float*)d_in[7];
    const float* bt = (const float*)d_in[8];
    float* out = (float*)d_out;

    float *p_degw, *p_dinv;
    int *p_cnt, *p_fill, *p_part, *p_bsum, *p_off;
    float2* p_meta;
    uint4 *p_a1h, *p_a1l, *p_h1h, *p_h1l, *p_w1h, *p_w1l, *p_w2h, *p_w2l;
    float4 *p_h2, *p_agg2;
    cudaGetSymbolAddress((void**)&p_degw, g_degw);
    cudaGetSymbolAddress((void**)&p_dinv, g_dinv);
    cudaGetSymbolAddress((void**)&p_cnt,  g_cnt);
    cudaGetSymbolAddress((void**)&p_fill, g_fill);
    cudaGetSymbolAddress((void**)&p_part, g_part);
    cudaGetSymbolAddress((void**)&p_bsum, g_bsum);
    cudaGetSymbolAddress((void**)&p_off,  g_off);
    cudaGetSymbolAddress((void**)&p_meta, g_meta);
    cudaGetSymbolAddress((void**)&p_a1h,  g_a1h);
    cudaGetSymbolAddress((void**)&p_a1l,  g_a1l);
    cudaGetSymbolAddress((void**)&p_h1h,  g_h1h);
    cudaGetSymbolAddress((void**)&p_h1l,  g_h1l);
    cudaGetSymbolAddress((void**)&p_w1h,  g_w1h);
    cudaGetSymbolAddress((void**)&p_w1l,  g_w1l);
    cudaGetSymbolAddress((void**)&p_w2h,  g_w2h);
    cudaGetSymbolAddress((void**)&p_w2l,  g_w2l);
    cudaGetSymbolAddress((void**)&p_h2,   g_h2);
    cudaGetSymbolAddress((void**)&p_agg2, g_agg2);

    // smem: (NOUT*(KTOT+8) + 128*136) * 2 planes * 2 bytes
    const int smem1 = (256 * 136 + 128 * 136) * 2 * 2;   // 208896
    const int smem2 = (128 * 264 + 128 * 136) * 2 * 2;   // 204800
    cudaFuncSetAttribute((const void*)k_gemm_mma<128, 256, 1>,
                         cudaFuncAttributeMaxDynamicSharedMemorySize, smem1);
    cudaFuncSetAttribute((const void*)k_gemm_mma<256, 128, 0>,
                         cudaFuncAttributeMaxDynamicSharedMemorySize, smem2);

    const int TB = 256;
    // weight splits (tiny, independent)
    k_prepW<<<(DHID * DIN / 8 + TB - 1) / TB, TB>>>(W1, p_w1h, p_w1l, DHID * DIN / 8);
    k_prepW<<<(DIN * DHID / 8 + TB - 1) / TB, TB>>>(W2, p_w2h, p_w2l, DIN * DHID / 8);

    // CSR build + norms
    k_zero <<<(NPAD + TB - 1) / TB, TB>>>(p_cnt, p_fill, p_degw);
    k_hist <<<(NE + TB - 1) / TB, TB>>>(ei, ew, p_cnt, p_degw);
    k_dinv <<<(NPAD + TB - 1) / TB, TB>>>(p_degw, p_dinv);
    k_scanA<<<SCAN_NBLK, SCAN_BS>>>(p_cnt, p_part, p_bsum);
    k_scanB<<<1, 64>>>(p_bsum);
    k_scanC<<<(NPAD + TB - 1) / TB, TB>>>(p_part, p_bsum, p_off);
    k_fill <<<(NE + TB - 1) / TB, TB>>>(ei, ew, p_dinv, p_off, p_fill, p_meta);

    // layer 1: aggregate x -> bf16 split; HMMA GEMM + bias + relu -> h1 split
    k_agg_csr<1><<<NPAD / 8, TB>>>(p_off, p_meta, p_dinv, x, nullptr,
                                   (uint32_t*)p_a1h, (uint32_t*)p_a1l);
    k_gemm_mma<128, 256, 1><<<NTILES, 512, smem1>>>(
        p_a1h, p_a1l, p_w1h, p_w1l, b1, (uint32_t*)p_h1h, (uint32_t*)p_h1l, nullptr);

    // layer 2: HMMA GEMM -> h2 fp32; aggregate -> agg2
    k_gemm_mma<256, 128, 0><<<NTILES, 512, smem2>>>(
        p_h1h, p_h1l, p_w2h, p_w2l, nullptr, nullptr, nullptr, (float*)p_h2);
    k_agg_csr<0><<<NPAD / 8, TB>>>(p_off, p_meta, p_dinv, (const float*)p_h2,
                                   (float*)p_agg2, nullptr, nullptr);

    // bias + LayerNorm
    k_layernorm<<<(NNODES * 32 + TB - 1) / TB, TB>>>(
        (const float*)p_agg2, b2, gm, bt, out);
}